// round 5
// baseline (speedup 1.0000x reference)
#include <cuda_runtime.h>
#include <math.h>

#define BB 4
#define NN 2048
#define KK 8
#define FF 2048

// ---------------- scratch (no allocations allowed) ----------------
__device__ int   g_idx[BB * NN * KK];                 // knn indices, (B,N,K)
__device__ float g_Mt[(size_t)BB * NN * FF];          // Mt[b][n][f] = mean of gathered neighbors
__device__ float g_trans[(size_t)BB * FF * NN];       // trans[b][f][m]
__device__ float g_mu[FF];
__device__ float g_rs[FF];

// ---------------- 1) KNN on (x,y), top-8 smallest, stable ties ----------------
// Bit-exact replication of the reference arithmetic:
//   xx[m]  = rn(x*x) + rn(y*y)                       (square then 2-elem reduce)
//   inner  = 2.0f * fma(y_n, y_m, rn(x_n*x_m))       (K=2 matmul fma-accumulate)
//   d      = (xx_n - inner) + xx_m                   (elementwise, left-to-right)
__global__ void knn_kernel(const float* __restrict__ xyz) {
    __shared__ float sx[NN], sy[NN], sxx[NN];
    int b = blockIdx.y;
    const float* xb = xyz + (size_t)b * NN * 3;
    for (int m = threadIdx.x; m < NN; m += blockDim.x) {
        float x = xb[m * 3 + 0];
        float y = xb[m * 3 + 1];
        sx[m] = x; sy[m] = y;
        sxx[m] = __fadd_rn(__fmul_rn(x, x), __fmul_rn(y, y));
    }
    __syncthreads();

    int n = blockIdx.x * blockDim.x + threadIdx.x;
    float xn = sx[n], yn = sy[n], xxn = sxx[n];

    float bestd[KK];
    int   besti[KK];
#pragma unroll
    for (int k = 0; k < KK; k++) { bestd[k] = INFINITY; besti[k] = -1; }

    for (int m = 0; m < NN; m++) {
        float p = __fmaf_rn(yn, sy[m], __fmul_rn(xn, sx[m]));
        float inner = __fmul_rn(2.0f, p);     // exact (power of two)
        float d = __fadd_rn(__fsub_rn(xxn, inner), sxx[m]);
        if (d < bestd[KK - 1]) {              // strict: equal keeps earlier index (stable)
            int pos = KK - 1;
#pragma unroll
            for (int t = 0; t < KK - 1; t++) {
                if (pos > 0 && d < bestd[pos - 1]) {
                    bestd[pos] = bestd[pos - 1];
                    besti[pos] = besti[pos - 1];
                    pos--;
                }
            }
            bestd[pos] = d; besti[pos] = m;
        }
    }
    int* out = g_idx + ((size_t)b * NN + n) * KK;
#pragma unroll
    for (int k = 0; k < KK; k++) out[k] = besti[k];
}

// ---------------- 2) Mt[b][n][f] = (1/8) sum_k feat[b, n, idx_flat[b][k*2048+f]] ----------------
__global__ void meangather_kernel(const float* __restrict__ feat) {
    __shared__ float row[NN];
    int b = blockIdx.y;
    int n = blockIdx.x;
    const float* fr = feat + ((size_t)b * FF + n) * NN;
    for (int i = threadIdx.x; i < NN; i += blockDim.x) row[i] = fr[i];
    __syncthreads();

    const int* idxb = g_idx + (size_t)b * NN * KK;   // flattened (N*K)
    float* outr = g_Mt + ((size_t)b * NN + n) * FF;
    for (int f = threadIdx.x; f < FF; f += blockDim.x) {
        float s = 0.f;
#pragma unroll
        for (int k = 0; k < KK; k++) {
            int c = idxb[k * NN + f];   // == idx[b][(k*2048+f)/8][(k*2048+f)%8]
            s += row[c];
        }
        outr[f] = s * (1.0f / KK);
    }
}

// ---------------- 3) SGEMM: trans[r][m] = sum_n (feat[r][n]-Mt[b][n][f]) * W[m][n] + b_lin[m] ----------------
#define BM 128
#define BN 128
#define BK 16

__global__ __launch_bounds__(256, 2) void gemm_kernel(const float* __restrict__ feat,
                                                      const float* __restrict__ W,
                                                      const float* __restrict__ b_lin) {
    __shared__ float As[BK][BM + 4];
    __shared__ float Bs[BK][BN + 4];

    int tid = threadIdx.x;
    int m0 = blockIdx.x * BN;
    int r0 = blockIdx.y * BM;
    int b  = r0 >> 11;           // FF = 2048
    int f0 = r0 & (FF - 1);

    const float* Arow = feat + (size_t)r0 * NN;
    const float* Mtb  = g_Mt + (size_t)b * NN * FF;

    int a_row = tid >> 2;            // 0..63  (rows a_row and a_row+64)
    int a_col = (tid & 3) * 4;       // 0,4,8,12
    int w_row = tid >> 1;            // 0..127
    int w_col = (tid & 1) * 8;       // 0 or 8
    int mt_k  = tid >> 4;            // 0..15
    int mt_m  = (tid & 15) * 8;      // 0..120

    int tx = tid & 15, ty = tid >> 4;

    float acc[8][8];
#pragma unroll
    for (int i = 0; i < 8; i++)
#pragma unroll
        for (int j = 0; j < 8; j++) acc[i][j] = 0.f;

    for (int kt = 0; kt < NN; kt += BK) {
        // feat -> As (transposed), n-coalesced
#pragma unroll
        for (int h = 0; h < 2; h++) {
            int rr = a_row + h * 64;
            float4 v = *(const float4*)(Arow + (size_t)rr * NN + kt + a_col);
            As[a_col + 0][rr] = v.x;
            As[a_col + 1][rr] = v.y;
            As[a_col + 2][rr] = v.z;
            As[a_col + 3][rr] = v.w;
        }
        // W -> Bs (transposed)
        {
            const float* wp = W + (size_t)(m0 + w_row) * NN + kt + w_col;
            float4 v0 = *(const float4*)(wp);
            float4 v1 = *(const float4*)(wp + 4);
            Bs[w_col + 0][w_row] = v0.x;
            Bs[w_col + 1][w_row] = v0.y;
            Bs[w_col + 2][w_row] = v0.z;
            Bs[w_col + 3][w_row] = v0.w;
            Bs[w_col + 4][w_row] = v1.x;
            Bs[w_col + 5][w_row] = v1.y;
            Bs[w_col + 6][w_row] = v1.z;
            Bs[w_col + 7][w_row] = v1.w;
        }
        __syncthreads();

        // fused laplacian: As[k][m] -= Mt[b][kt+k][f0+m]  (f-coalesced)
        {
            const float* mp = Mtb + (size_t)(kt + mt_k) * FF + f0 + mt_m;
            float4 u0 = *(const float4*)(mp);
            float4 u1 = *(const float4*)(mp + 4);
            float4* asp = (float4*)&As[mt_k][mt_m];
            float4 a0 = asp[0], a1 = asp[1];
            a0.x -= u0.x; a0.y -= u0.y; a0.z -= u0.z; a0.w -= u0.w;
            a1.x -= u1.x; a1.y -= u1.y; a1.z -= u1.z; a1.w -= u1.w;
            asp[0] = a0; asp[1] = a1;
        }
        __syncthreads();

#pragma unroll
        for (int k = 0; k < BK; k++) {
            float a[8], br[8];
#pragma unroll
            for (int i = 0; i < 8; i++) a[i] = As[k][ty * 8 + i];
#pragma unroll
            for (int j = 0; j < 8; j++) br[j] = Bs[k][tx * 8 + j];
#pragma unroll
            for (int i = 0; i < 8; i++)
#pragma unroll
                for (int j = 0; j < 8; j++) acc[i][j] += a[i] * br[j];
        }
        __syncthreads();
    }

    // epilogue: + b_lin, write trans
    float bl[8];
#pragma unroll
    for (int j = 0; j < 8; j++) bl[j] = b_lin[m0 + tx * 8 + j];

#pragma unroll
    for (int i = 0; i < 8; i++) {
        int r = r0 + ty * 8 + i;
        float* outp = g_trans + (size_t)r * NN + m0 + tx * 8;
        float4 o0, o1;
        o0.x = acc[i][0] + bl[0]; o0.y = acc[i][1] + bl[1];
        o0.z = acc[i][2] + bl[2]; o0.w = acc[i][3] + bl[3];
        o1.x = acc[i][4] + bl[4]; o1.y = acc[i][5] + bl[5];
        o1.z = acc[i][6] + bl[6]; o1.w = acc[i][7] + bl[7];
        ((float4*)outp)[0] = o0;
        ((float4*)outp)[1] = o1;
    }
}

// ---------------- 4) per-f BN stats over (b, m) ----------------
__global__ void bnstats_kernel() {
    int f = blockIdx.x;
    int tid = threadIdx.x;
    float s = 0.f, s2 = 0.f;
    for (int b = 0; b < BB; b++) {
        const float* tr = g_trans + ((size_t)b * FF + f) * (size_t)NN;
        for (int m = tid; m < NN; m += 256) {
            float v = tr[m];
            s += v; s2 += v * v;
        }
    }
#pragma unroll
    for (int o = 16; o > 0; o >>= 1) {
        s  += __shfl_down_sync(0xffffffffu, s,  o);
        s2 += __shfl_down_sync(0xffffffffu, s2, o);
    }
    __shared__ float sh[64];
    int w = tid >> 5, l = tid & 31;
    if (l == 0) { sh[w] = s; sh[32 + w] = s2; }
    __syncthreads();
    if (tid == 0) {
        float S = 0.f, S2 = 0.f;
#pragma unroll
        for (int i = 0; i < 8; i++) { S += sh[i]; S2 += sh[32 + i]; }
        const float inv = 1.0f / (float)(BB * NN);
        float mu = S * inv;
        float var = S2 * inv - mu * mu;
        g_mu[f] = mu;
        g_rs[f] = 1.0f / sqrtf(var + 1e-5f);
    }
}

// ---------------- 5) out = feat + relu((trans - mu) * rs) ----------------
__global__ void final_kernel(const float* __restrict__ feat, float* __restrict__ out) {
    size_t i4 = (size_t)blockIdx.x * blockDim.x + threadIdx.x;
    const size_t total4 = (size_t)BB * FF * NN / 4;
    if (i4 >= total4) return;
    size_t base = i4 * 4;
    int f = (int)((base >> 11) & (FF - 1));
    float mu = g_mu[f], rs = g_rs[f];
    float4 t  = ((const float4*)g_trans)[i4];
    float4 fe = ((const float4*)feat)[i4];
    float4 o;
    o.x = fe.x + fmaxf(0.f, (t.x - mu) * rs);
    o.y = fe.y + fmaxf(0.f, (t.y - mu) * rs);
    o.z = fe.z + fmaxf(0.f, (t.z - mu) * rs);
    o.w = fe.w + fmaxf(0.f, (t.w - mu) * rs);
    ((float4*)out)[i4] = o;
}

// ---------------- launch ----------------
extern "C" void kernel_launch(void* const* d_in, const int* in_sizes, int n_in,
                              void* d_out, int out_size) {
    const float* xyz   = (const float*)d_in[0];   // (B, N, 3)
    const float* feat  = (const float*)d_in[1];   // (B, F, N)
    const float* W     = (const float*)d_in[2];   // (N, N)
    const float* b_lin = (const float*)d_in[3];   // (N,)
    float* out = (float*)d_out;

    (void)in_sizes; (void)n_in; (void)out_size;

    knn_kernel<<<dim3(NN / 256, BB), 256>>>(xyz);
    meangather_kernel<<<dim3(NN, BB), 256>>>(feat);
    gemm_kernel<<<dim3(NN / BN, (BB * FF) / BM), 256>>>(feat, W, b_lin);
    bnstats_kernel<<<FF, 256>>>();
    {
        size_t total4 = (size_t)BB * FF * NN / 4;
        int blocks = (int)((total4 + 255) / 256);
        final_kernel<<<blocks, 256>>>(feat, out);
    }
}

// round 12
// speedup vs baseline: 1.6743x; 1.6743x over previous
#include <cuda_runtime.h>
#include <cuda_bf16.h>
#include <math.h>

#define BB 4
#define NN 2048
#define KK 8
#define FF 2048

// ---------------- scratch (no allocations allowed) ----------------
__device__ int   g_idx[BB * NN * KK];
__device__ float g_Mt [(size_t)BB * NN * FF];    // Mt[b][n][f]
__device__ float g_MtT[(size_t)BB * NN * FF];    // MtT[b][f][n]  (== index r*NN+n, r=b*FF+f)
__device__ float g_trans[(size_t)BB * FF * NN];  // trans[r][m]
__device__ float g_mu[FF];
__device__ float g_rs[FF];

// ---------------- 1) KNN on (x,y), top-8 smallest, stable ties ----------------
__global__ void knn_kernel(const float* __restrict__ xyz) {
    __shared__ float sx[NN], sy[NN], sxx[NN];
    int b = blockIdx.y;
    const float* xb = xyz + (size_t)b * NN * 3;
    for (int m = threadIdx.x; m < NN; m += blockDim.x) {
        float x = xb[m * 3 + 0];
        float y = xb[m * 3 + 1];
        sx[m] = x; sy[m] = y;
        sxx[m] = __fadd_rn(__fmul_rn(x, x), __fmul_rn(y, y));
    }
    __syncthreads();

    int n = blockIdx.x * blockDim.x + threadIdx.x;
    float xn = sx[n], yn = sy[n], xxn = sxx[n];

    float bestd[KK];
    int   besti[KK];
#pragma unroll
    for (int k = 0; k < KK; k++) { bestd[k] = INFINITY; besti[k] = -1; }

    for (int m = 0; m < NN; m++) {
        float p = __fmaf_rn(yn, sy[m], __fmul_rn(xn, sx[m]));
        float inner = __fmul_rn(2.0f, p);
        float d = __fadd_rn(__fsub_rn(xxn, inner), sxx[m]);
        if (d < bestd[KK - 1]) {
            int pos = KK - 1;
#pragma unroll
            for (int t = 0; t < KK - 1; t++) {
                if (pos > 0 && d < bestd[pos - 1]) {
                    bestd[pos] = bestd[pos - 1];
                    besti[pos] = besti[pos - 1];
                    pos--;
                }
            }
            bestd[pos] = d; besti[pos] = m;
        }
    }
    int* out = g_idx + ((size_t)b * NN + n) * KK;
#pragma unroll
    for (int k = 0; k < KK; k++) out[k] = besti[k];
}

// ---------------- 2) Mt[b][n][f] = (1/8) sum_k feat[b, n, idx_flat[b][k*2048+f]] ----------------
__global__ void meangather_kernel(const float* __restrict__ feat) {
    __shared__ float row[NN];
    int b = blockIdx.y;
    int n = blockIdx.x;
    const float* fr = feat + ((size_t)b * FF + n) * NN;
    for (int i = threadIdx.x; i < NN; i += blockDim.x) row[i] = fr[i];
    __syncthreads();

    const int* idxb = g_idx + (size_t)b * NN * KK;
    float* outr = g_Mt + ((size_t)b * NN + n) * FF;
    for (int f = threadIdx.x; f < FF; f += blockDim.x) {
        float s = 0.f;
#pragma unroll
        for (int k = 0; k < KK; k++) {
            int c = idxb[k * NN + f];
            s += row[c];
        }
        outr[f] = s * (1.0f / KK);
    }
}

// ---------------- 2b) transpose Mt[b][n][f] -> MtT[b][f][n] ----------------
__global__ void transpose_kernel() {
    __shared__ float t[32][33];
    int b = blockIdx.z;
    int n0 = blockIdx.x * 32, f0 = blockIdx.y * 32;
    const float* src = g_Mt  + (size_t)b * NN * FF;
    float*       dst = g_MtT + (size_t)b * NN * FF;
    int tx = threadIdx.x, ty = threadIdx.y;   // 32 x 8
#pragma unroll
    for (int j = 0; j < 4; j++)
        t[ty + j * 8][tx] = src[(size_t)(n0 + ty + j * 8) * FF + f0 + tx];
    __syncthreads();
#pragma unroll
    for (int j = 0; j < 4; j++)
        dst[(size_t)(f0 + ty + j * 8) * NN + n0 + tx] = t[tx][ty + j * 8];
}

// ---------------- 3) bf16-split tensor-core GEMM ----------------
// trans[r][m] = sum_n lap[r][n] * W[m][n] + b_lin[m],  lap = feat - MtT (same index)
#define KT 32          // k-tile
#define PAD 40         // smem row stride in halves (80B: ldmatrix conflict-free)

__device__ __forceinline__ void ldsm4(unsigned& r0, unsigned& r1, unsigned& r2, unsigned& r3,
                                      const void* p) {
    unsigned a = (unsigned)__cvta_generic_to_shared(p);
    asm volatile("ldmatrix.sync.aligned.m8n8.x4.shared.b16 {%0,%1,%2,%3}, [%4];"
                 : "=r"(r0), "=r"(r1), "=r"(r2), "=r"(r3) : "r"(a));
}
__device__ __forceinline__ void mma16816(float* c, const unsigned* a, const unsigned* b) {
    asm volatile("mma.sync.aligned.m16n8k16.row.col.f32.bf16.bf16.f32 "
                 "{%0,%1,%2,%3}, {%4,%5,%6,%7}, {%8,%9}, {%0,%1,%2,%3};"
                 : "+f"(c[0]), "+f"(c[1]), "+f"(c[2]), "+f"(c[3])
                 : "r"(a[0]), "r"(a[1]), "r"(a[2]), "r"(a[3]), "r"(b[0]), "r"(b[1]));
}

// split v into hi(bf16) + lo(bf16 of residual); store pairs at dst[0..3]
__device__ __forceinline__ void split_store4(__nv_bfloat16* dh, __nv_bfloat16* dl,
                                             float a, float b, float c, float d) {
    __nv_bfloat162 h0 = __floats2bfloat162_rn(a, b);
    __nv_bfloat162 h1 = __floats2bfloat162_rn(c, d);
    float ra = a - __low2float(h0),  rb = b - __high2float(h0);
    float rc = c - __low2float(h1),  rd = d - __high2float(h1);
    *(__nv_bfloat162*)(dh)     = h0;
    *(__nv_bfloat162*)(dh + 2) = h1;
    *(__nv_bfloat162*)(dl)     = __floats2bfloat162_rn(ra, rb);
    *(__nv_bfloat162*)(dl + 2) = __floats2bfloat162_rn(rc, rd);
}

__global__ __launch_bounds__(256, 1) void gemm_mma_kernel(const float* __restrict__ feat,
                                                          const float* __restrict__ W,
                                                          const float* __restrict__ b_lin) {
    __shared__ __align__(16) __nv_bfloat16 As_h[128][PAD];
    __shared__ __align__(16) __nv_bfloat16 As_l[128][PAD];
    __shared__ __align__(16) __nv_bfloat16 Bs_h[128][PAD];
    __shared__ __align__(16) __nv_bfloat16 Bs_l[128][PAD];

    const int tid  = threadIdx.x;
    const int lane = tid & 31;
    const int w    = tid >> 5;
    const int m0 = blockIdx.x * 128;
    const int r0 = blockIdx.y * 128;

    const int wm0 = (w >> 2) * 64;   // 0 or 64
    const int wn0 = (w & 3) * 32;    // 0,32,64,96

    float acc[4][4][4];
#pragma unroll
    for (int i = 0; i < 4; i++)
#pragma unroll
        for (int j = 0; j < 4; j++)
#pragma unroll
            for (int q = 0; q < 4; q++) acc[i][j][q] = 0.f;

    const int lrow  = lane & 15;
    const int lcolA = (lane >> 4) * 8;
    const int g8    = lane >> 3;
    const int l8    = lane & 7;
    const int brow  = ((g8 >> 1) & 1) * 8 + l8;
    const int bcolo = (g8 & 1) * 8;

    for (int kt = 0; kt < NN; kt += KT) {
        // ---- stage A = feat - MtT (split), and B = W (split) ----
#pragma unroll
        for (int h = 0; h < 4; h++) {
            int flat = h * 256 + tid;         // 0..1023
            int rr = flat >> 3;               // 0..127
            int kc = (flat & 7) * 4;          // 0..28
            size_t off = (size_t)(r0 + rr) * NN + kt + kc;
            float4 fv = *(const float4*)(feat + off);
            float4 mv = *(const float4*)(g_MtT + off);
            split_store4(&As_h[rr][kc], &As_l[rr][kc],
                         fv.x - mv.x, fv.y - mv.y, fv.z - mv.z, fv.w - mv.w);
            float4 wv = *(const float4*)(W + (size_t)(m0 + rr) * NN + kt + kc);
            split_store4(&Bs_h[rr][kc], &Bs_l[rr][kc], wv.x, wv.y, wv.z, wv.w);
        }
        __syncthreads();

        // ---- compute ----
#pragma unroll
        for (int ks = 0; ks < KT; ks += 16) {
            unsigned ah[4][4], al[4][4], bh[4][2], bl[4][2];
#pragma unroll
            for (int i = 0; i < 4; i++) {
                ldsm4(ah[i][0], ah[i][1], ah[i][2], ah[i][3],
                      &As_h[wm0 + i * 16 + lrow][ks + lcolA]);
                ldsm4(al[i][0], al[i][1], al[i][2], al[i][3],
                      &As_l[wm0 + i * 16 + lrow][ks + lcolA]);
            }
            // B fragments: Bs is [n][k] (k contiguous) and the mma B operand wants
            // consecutive-k pairs at fixed n -> NON-trans ldmatrix with n-row addresses.
            // matrices: 0 = n[0:8]k[0:8], 1 = n[0:8]k[8:16], 2 = n[8:16]k[0:8], 3 = n[8:16]k[8:16]
#pragma unroll
            for (int jj = 0; jj < 2; jj++) {
                unsigned t0, t1, t2, t3;
                ldsm4(t0, t1, t2, t3, &Bs_h[wn0 + jj * 16 + brow][ks + bcolo]);
                bh[jj * 2][0] = t0; bh[jj * 2][1] = t1;
                bh[jj * 2 + 1][0] = t2; bh[jj * 2 + 1][1] = t3;
                ldsm4(t0, t1, t2, t3, &Bs_l[wn0 + jj * 16 + brow][ks + bcolo]);
                bl[jj * 2][0] = t0; bl[jj * 2][1] = t1;
                bl[jj * 2 + 1][0] = t2; bl[jj * 2 + 1][1] = t3;
            }
#pragma unroll
            for (int i = 0; i < 4; i++)
#pragma unroll
                for (int j = 0; j < 4; j++) {
                    mma16816(acc[i][j], ah[i], bh[j]);   // hi*hi
                    mma16816(acc[i][j], ah[i], bl[j]);   // hi*lo
                    mma16816(acc[i][j], al[i], bh[j]);   // lo*hi
                }
        }
        __syncthreads();
    }

    // ---- epilogue: + b_lin, write trans ----
#pragma unroll
    for (int j = 0; j < 4; j++) {
        int col = wn0 + j * 8 + (lane & 3) * 2;
        float bl0 = b_lin[m0 + col];
        float bl1 = b_lin[m0 + col + 1];
#pragma unroll
        for (int i = 0; i < 4; i++) {
            int row0 = wm0 + i * 16 + (lane >> 2);
            float2 v0 = make_float2(acc[i][j][0] + bl0, acc[i][j][1] + bl1);
            float2 v1 = make_float2(acc[i][j][2] + bl0, acc[i][j][3] + bl1);
            *(float2*)(g_trans + (size_t)(r0 + row0) * NN + m0 + col) = v0;
            *(float2*)(g_trans + (size_t)(r0 + row0 + 8) * NN + m0 + col) = v1;
        }
    }
}

// ---------------- 4) per-f BN stats over (b, m) ----------------
__global__ void bnstats_kernel() {
    int f = blockIdx.x;
    int tid = threadIdx.x;
    float s = 0.f, s2 = 0.f;
    for (int b = 0; b < BB; b++) {
        const float* tr = g_trans + ((size_t)b * FF + f) * (size_t)NN;
        for (int m = tid; m < NN; m += 256) {
            float v = tr[m];
            s += v; s2 += v * v;
        }
    }
#pragma unroll
    for (int o = 16; o > 0; o >>= 1) {
        s  += __shfl_down_sync(0xffffffffu, s,  o);
        s2 += __shfl_down_sync(0xffffffffu, s2, o);
    }
    __shared__ float sh[64];
    int w = tid >> 5, l = tid & 31;
    if (l == 0) { sh[w] = s; sh[32 + w] = s2; }
    __syncthreads();
    if (tid == 0) {
        float S = 0.f, S2 = 0.f;
#pragma unroll
        for (int i = 0; i < 8; i++) { S += sh[i]; S2 += sh[32 + i]; }
        const float inv = 1.0f / (float)(BB * NN);
        float mu = S * inv;
        float var = S2 * inv - mu * mu;
        g_mu[f] = mu;
        g_rs[f] = 1.0f / sqrtf(var + 1e-5f);
    }
}

// ---------------- 5) out = feat + relu((trans - mu) * rs) ----------------
__global__ void final_kernel(const float* __restrict__ feat, float* __restrict__ out) {
    size_t i4 = (size_t)blockIdx.x * blockDim.x + threadIdx.x;
    const size_t total4 = (size_t)BB * FF * NN / 4;
    if (i4 >= total4) return;
    size_t base = i4 * 4;
    int f = (int)((base >> 11) & (FF - 1));
    float mu = g_mu[f], rs = g_rs[f];
    float4 t  = ((const float4*)g_trans)[i4];
    float4 fe = ((const float4*)feat)[i4];
    float4 o;
    o.x = fe.x + fmaxf(0.f, (t.x - mu) * rs);
    o.y = fe.y + fmaxf(0.f, (t.y - mu) * rs);
    o.z = fe.z + fmaxf(0.f, (t.z - mu) * rs);
    o.w = fe.w + fmaxf(0.f, (t.w - mu) * rs);
    ((float4*)out)[i4] = o;
}

// ---------------- launch ----------------
extern "C" void kernel_launch(void* const* d_in, const int* in_sizes, int n_in,
                              void* d_out, int out_size) {
    const float* xyz   = (const float*)d_in[0];
    const float* feat  = (const float*)d_in[1];
    const float* W     = (const float*)d_in[2];
    const float* b_lin = (const float*)d_in[3];
    float* out = (float*)d_out;

    (void)in_sizes; (void)n_in; (void)out_size;

    knn_kernel<<<dim3(NN / 256, BB), 256>>>(xyz);
    meangather_kernel<<<dim3(NN, BB), 256>>>(feat);
    transpose_kernel<<<dim3(NN / 32, FF / 32, BB), dim3(32, 8)>>>();
    gemm_mma_kernel<<<dim3(NN / 128, (BB * FF) / 128), 256>>>(feat, W, b_lin);
    bnstats_kernel<<<FF, 256>>>();
    {
        size_t total4 = (size_t)BB * FF * NN / 4;
        int blocks = (int)((total4 + 255) / 256);
        final_kernel<<<blocks, 256>>>(feat, out);
    }
}